// round 9
// baseline (speedup 1.0000x reference)
#include <cuda_runtime.h>
#include <math.h>

#define N_B   2
#define C_    256
#define L_    4096
#define G_    8
#define CPG   32
#define HEADS 4
#define HD    64
#define EPSV  1e-5f
#define NCL   (N_B * C_ * L_)   // 2097152

// ---------------- scratch (static device globals; no allocation) ------------
__device__ float g_xn[NCL];
__device__ float g_q [NCL];
__device__ float g_k [NCL];
__device__ float g_v [NCL];
__device__ float g_ao[NCL];
__device__ float g_stats[N_B * G_ * 2];   // mean, rstd per (n,g)

// ---------------- GroupNorm: stats ------------------------------------------
__global__ void gn_stats_kernel(const float* __restrict__ x) {
    int ng = blockIdx.x;  // 0..15 : n*8+g, groups are contiguous channel blocks
    const float4* base = (const float4*)(x + (size_t)ng * CPG * L_);
    float s1 = 0.f, s2 = 0.f;
    const int nv = CPG * L_ / 4;  // 32768
    for (int i = threadIdx.x; i < nv; i += 256) {
        float4 v = base[i];
        s1 += (v.x + v.y) + (v.z + v.w);
        s2 += (v.x * v.x + v.y * v.y) + (v.z * v.z + v.w * v.w);
    }
    __shared__ float r1[256], r2[256];
    r1[threadIdx.x] = s1; r2[threadIdx.x] = s2;
    __syncthreads();
    for (int s = 128; s > 0; s >>= 1) {
        if (threadIdx.x < s) {
            r1[threadIdx.x] += r1[threadIdx.x + s];
            r2[threadIdx.x] += r2[threadIdx.x + s];
        }
        __syncthreads();
    }
    if (threadIdx.x == 0) {
        float cnt  = (float)(CPG * L_);
        float mean = r1[0] / cnt;
        float var  = r2[0] / cnt - mean * mean;
        g_stats[ng * 2 + 0] = mean;
        g_stats[ng * 2 + 1] = rsqrtf(var + EPSV);
    }
}

// ---------------- GroupNorm: apply ------------------------------------------
__global__ void gn_apply_kernel(const float* __restrict__ x,
                                const float* __restrict__ w,
                                const float* __restrict__ b) {
    int i = blockIdx.x * blockDim.x + threadIdx.x;
    if (i >= NCL / 4) return;
    int e  = i * 4;
    int c  = (e / L_) & (C_ - 1);
    int ng = e / (CPG * L_);
    float mean = g_stats[ng * 2 + 0], rstd = g_stats[ng * 2 + 1];
    float sw = w[c] * rstd;
    float sb = b[c] - mean * sw;
    float4 xv = ((const float4*)x)[i];
    float4 o;
    o.x = xv.x * sw + sb; o.y = xv.y * sw + sb;
    o.z = xv.z * sw + sb; o.w = xv.w * sw + sb;
    ((float4*)g_xn)[i] = o;
}

// ---------------- QKV conv1x1 GEMM: out[d,l] = sum_c w[d,c]*xn[c,l] + b[d] --
// tile 64x64, K-step 16, 256 threads, 4x4 micro-tile per thread
__global__ void __launch_bounds__(256) gemm_qkv_kernel(
    const float* __restrict__ qw, const float* __restrict__ qb,
    const float* __restrict__ kw, const float* __restrict__ kb,
    const float* __restrict__ vw, const float* __restrict__ vb) {

    int z = blockIdx.z;            // 0..5
    int batch = z / 3, which = z - batch * 3;
    const float* w; const float* bia; float* outp;
    if      (which == 0) { w = qw; bia = qb; outp = g_q; }
    else if (which == 1) { w = kw; bia = kb; outp = g_k; }
    else                 { w = vw; bia = vb; outp = g_v; }

    const float* B   = g_xn + (size_t)batch * C_ * L_;
    float*       Out = outp + (size_t)batch * C_ * L_;
    int m0 = blockIdx.y * 64, n0 = blockIdx.x * 64;

    __shared__ __align__(16) float As[16][68];
    __shared__ __align__(16) float Bs[16][64];

    int tx = threadIdx.x & 15, ty = threadIdx.x >> 4;
    float acc[4][4];
#pragma unroll
    for (int a = 0; a < 4; a++)
#pragma unroll
        for (int c = 0; c < 4; c++) acc[a][c] = 0.f;

    for (int k0 = 0; k0 < C_; k0 += 16) {
#pragma unroll
        for (int it = 0; it < 4; ++it) {
            int idx = threadIdx.x + it * 256;
            int kk = idx & 15, mm = idx >> 4;
            As[kk][mm] = w[(m0 + mm) * C_ + k0 + kk];
        }
#pragma unroll
        for (int it = 0; it < 4; ++it) {
            int idx = threadIdx.x + it * 256;
            int nn = idx & 63, kk = idx >> 6;
            Bs[kk][nn] = B[(size_t)(k0 + kk) * L_ + n0 + nn];
        }
        __syncthreads();
#pragma unroll
        for (int kk = 0; kk < 16; kk++) {
            float4 aa = *(const float4*)&As[kk][ty * 4];
            float4 bb = *(const float4*)&Bs[kk][tx * 4];
            acc[0][0] += aa.x * bb.x; acc[0][1] += aa.x * bb.y; acc[0][2] += aa.x * bb.z; acc[0][3] += aa.x * bb.w;
            acc[1][0] += aa.y * bb.x; acc[1][1] += aa.y * bb.y; acc[1][2] += aa.y * bb.z; acc[1][3] += aa.y * bb.w;
            acc[2][0] += aa.z * bb.x; acc[2][1] += aa.z * bb.y; acc[2][2] += aa.z * bb.z; acc[2][3] += aa.z * bb.w;
            acc[3][0] += aa.w * bb.x; acc[3][1] += aa.w * bb.y; acc[3][2] += aa.w * bb.z; acc[3][3] += aa.w * bb.w;
        }
        __syncthreads();
    }
#pragma unroll
    for (int im = 0; im < 4; im++) {
        int m = m0 + ty * 4 + im;
        float bv = bia[m];
        float4 o;
        o.x = acc[im][0] + bv; o.y = acc[im][1] + bv;
        o.z = acc[im][2] + bv; o.w = acc[im][3] + bv;
        *(float4*)&Out[(size_t)m * L_ + n0 + tx * 4] = o;
    }
}

// ---------------- Flash attention: Bq=64, Bk=32, online softmax -------------
__global__ void __launch_bounds__(256) attn_kernel() {
    int l0 = blockIdx.x * 64;
    int h  = blockIdx.y;
    int n  = blockIdx.z;
    int chbase = n * C_ + h * HD;
    const float* qp = g_q + (size_t)chbase * L_;
    const float* kp = g_k + (size_t)chbase * L_;
    const float* vp = g_v + (size_t)chbase * L_;

    __shared__ __align__(16) float Qs[64 * 68];
    __shared__ __align__(16) float Ks[64 * 34];
    __shared__ __align__(16) float Vs[32 * 68];
    __shared__ __align__(16) float Ps[32 * 68];

    int t  = threadIdx.x;
    int tx = t & 15, ty = t >> 4;

    // load Q tile [c][i], c=0..63, i=0..63
#pragma unroll
    for (int it = 0; it < 16; ++it) {
        int idx = t + it * 256;
        int c = idx >> 6, i = idx & 63;
        Qs[c * 68 + i] = qp[(size_t)c * L_ + l0 + i];
    }

    float O[4][4];     // [cc][r] : c = tx*4+cc, i = ty*4+r
    float m_run[4], l_run[4];
#pragma unroll
    for (int r = 0; r < 4; r++) {
        m_run[r] = -INFINITY; l_run[r] = 0.f;
#pragma unroll
        for (int cc = 0; cc < 4; cc++) O[cc][r] = 0.f;
    }
    __syncthreads();

    const float scale = 0.125f;   // hd^-0.5, hd=64

    for (int kt = 0; kt < 128; ++kt) {
        int k0 = kt * 32;
        // load K [c][j] and V transposed [j][c]
#pragma unroll
        for (int it = 0; it < 8; ++it) {
            int idx = t + it * 256;
            int c = idx >> 5, j = idx & 31;
            float kvk = kp[(size_t)c * L_ + k0 + j];
            float kvv = vp[(size_t)c * L_ + k0 + j];
            Ks[c * 34 + j] = kvk;
            Vs[j * 68 + c] = kvv;
        }
        __syncthreads();

        // S[i][j] = sum_c Q[c][i]*K[c][j] ; thread: 4 rows x 2 cols
        float s00 = 0.f, s01 = 0.f, s10 = 0.f, s11 = 0.f;
        float s20 = 0.f, s21 = 0.f, s30 = 0.f, s31 = 0.f;
#pragma unroll 16
        for (int c = 0; c < 64; c++) {
            float4 qa = *(const float4*)&Qs[c * 68 + ty * 4];
            float2 kb = *(const float2*)&Ks[c * 34 + tx * 2];
            s00 += qa.x * kb.x; s01 += qa.x * kb.y;
            s10 += qa.y * kb.x; s11 += qa.y * kb.y;
            s20 += qa.z * kb.x; s21 += qa.z * kb.y;
            s30 += qa.w * kb.x; s31 += qa.w * kb.y;
        }
        float sv[4][2] = {{s00, s01}, {s10, s11}, {s20, s21}, {s30, s31}};

        // online softmax per query row (16 lanes with same ty hold one row)
#pragma unroll
        for (int r = 0; r < 4; r++) {
            float v0 = sv[r][0] * scale, v1 = sv[r][1] * scale;
            float mloc = fmaxf(v0, v1);
#pragma unroll
            for (int off = 8; off > 0; off >>= 1)
                mloc = fmaxf(mloc, __shfl_xor_sync(0xffffffffu, mloc, off));
            float mnew  = fmaxf(m_run[r], mloc);
            float alpha = __expf(m_run[r] - mnew);
            float p0 = __expf(v0 - mnew);
            float p1 = __expf(v1 - mnew);
            float sl = p0 + p1;
#pragma unroll
            for (int off = 8; off > 0; off >>= 1)
                sl += __shfl_xor_sync(0xffffffffu, sl, off);
            l_run[r] = l_run[r] * alpha + sl;
            m_run[r] = mnew;
#pragma unroll
            for (int cc = 0; cc < 4; cc++) O[cc][r] *= alpha;
            Ps[(tx * 2 + 0) * 68 + ty * 4 + r] = p0;
            Ps[(tx * 2 + 1) * 68 + ty * 4 + r] = p1;
        }
        __syncthreads();

        // O[c][i] += sum_j V[c][j]*P[i][j]
#pragma unroll 8
        for (int j = 0; j < 32; j++) {
            float4 va = *(const float4*)&Vs[j * 68 + tx * 4];
            float4 pa = *(const float4*)&Ps[j * 68 + ty * 4];
            O[0][0] += va.x * pa.x; O[0][1] += va.x * pa.y; O[0][2] += va.x * pa.z; O[0][3] += va.x * pa.w;
            O[1][0] += va.y * pa.x; O[1][1] += va.y * pa.y; O[1][2] += va.y * pa.z; O[1][3] += va.y * pa.w;
            O[2][0] += va.z * pa.x; O[2][1] += va.z * pa.y; O[2][2] += va.z * pa.z; O[2][3] += va.z * pa.w;
            O[3][0] += va.w * pa.x; O[3][1] += va.w * pa.y; O[3][2] += va.w * pa.z; O[3][3] += va.w * pa.w;
        }
        __syncthreads();
    }

    // normalize and store
    float* ao = g_ao + (size_t)chbase * L_;
#pragma unroll
    for (int r = 0; r < 4; r++) {
        float inv = 1.f / l_run[r];
#pragma unroll
        for (int cc = 0; cc < 4; cc++)
            ao[(size_t)(tx * 4 + cc) * L_ + l0 + ty * 4 + r] = O[cc][r] * inv;
    }
}

// ---------------- projection + bias + residual ------------------------------
__global__ void __launch_bounds__(256) gemm_proj_kernel(
    const float* __restrict__ x,
    const float* __restrict__ pw, const float* __restrict__ pb,
    float* __restrict__ out) {

    int batch = blockIdx.z;
    const float* B  = g_ao + (size_t)batch * C_ * L_;
    const float* xb = x    + (size_t)batch * C_ * L_;
    float*       Ob = out  + (size_t)batch * C_ * L_;
    int m0 = blockIdx.y * 64, n0 = blockIdx.x * 64;

    __shared__ __align__(16) float As[16][68];
    __shared__ __align__(16) float Bs[16][64];

    int tx = threadIdx.x & 15, ty = threadIdx.x >> 4;
    float acc[4][4];
#pragma unroll
    for (int a = 0; a < 4; a++)
#pragma unroll
        for (int c = 0; c < 4; c++) acc[a][c] = 0.f;

    for (int k0 = 0; k0 < C_; k0 += 16) {
#pragma unroll
        for (int it = 0; it < 4; ++it) {
            int idx = threadIdx.x + it * 256;
            int kk = idx & 15, mm = idx >> 4;
            As[kk][mm] = pw[(m0 + mm) * C_ + k0 + kk];
        }
#pragma unroll
        for (int it = 0; it < 4; ++it) {
            int idx = threadIdx.x + it * 256;
            int nn = idx & 63, kk = idx >> 6;
            Bs[kk][nn] = B[(size_t)(k0 + kk) * L_ + n0 + nn];
        }
        __syncthreads();
#pragma unroll
        for (int kk = 0; kk < 16; kk++) {
            float4 aa = *(const float4*)&As[kk][ty * 4];
            float4 bb = *(const float4*)&Bs[kk][tx * 4];
            acc[0][0] += aa.x * bb.x; acc[0][1] += aa.x * bb.y; acc[0][2] += aa.x * bb.z; acc[0][3] += aa.x * bb.w;
            acc[1][0] += aa.y * bb.x; acc[1][1] += aa.y * bb.y; acc[1][2] += aa.y * bb.z; acc[1][3] += aa.y * bb.w;
            acc[2][0] += aa.z * bb.x; acc[2][1] += aa.z * bb.y; acc[2][2] += aa.z * bb.z; acc[2][3] += aa.z * bb.w;
            acc[3][0] += aa.w * bb.x; acc[3][1] += aa.w * bb.y; acc[3][2] += aa.w * bb.z; acc[3][3] += aa.w * bb.w;
        }
        __syncthreads();
    }
#pragma unroll
    for (int im = 0; im < 4; im++) {
        int m = m0 + ty * 4 + im;
        float bv = pb[m];
        size_t off = (size_t)m * L_ + n0 + tx * 4;
        float4 xv = *(const float4*)&xb[off];
        float4 o;
        o.x = acc[im][0] + bv + xv.x; o.y = acc[im][1] + bv + xv.y;
        o.z = acc[im][2] + bv + xv.z; o.w = acc[im][3] + bv + xv.w;
        *(float4*)&Ob[off] = o;
    }
}

// ---------------- mask pass-through (int32 -> float) ------------------------
__global__ void mask_copy_kernel(const int* __restrict__ mask,
                                 float* __restrict__ out, int nmask) {
    int i = blockIdx.x * blockDim.x + threadIdx.x;
    if (i < nmask) out[NCL + i] = (float)mask[i];
}

// ---------------- launch -----------------------------------------------------
extern "C" void kernel_launch(void* const* d_in, const int* in_sizes, int n_in,
                              void* d_out, int out_size) {
    const float* x    = (const float*)d_in[0];
    const int*   mask = (const int*)  d_in[1];
    const float* nw   = (const float*)d_in[2];
    const float* nb   = (const float*)d_in[3];
    const float* qw   = (const float*)d_in[4];
    const float* qb   = (const float*)d_in[5];
    const float* kw   = (const float*)d_in[6];
    const float* kb   = (const float*)d_in[7];
    const float* vw   = (const float*)d_in[8];
    const float* vb   = (const float*)d_in[9];
    const float* pw   = (const float*)d_in[10];
    const float* pb   = (const float*)d_in[11];
    float* out = (float*)d_out;

    gn_stats_kernel<<<N_B * G_, 256>>>(x);
    gn_apply_kernel<<<(NCL / 4 + 255) / 256, 256>>>(x, nw, nb);

    dim3 gq(L_ / 64, C_ / 64, N_B * 3);
    gemm_qkv_kernel<<<gq, 256>>>(qw, qb, kw, kb, vw, vb);

    dim3 ga(L_ / 64, HEADS, N_B);
    attn_kernel<<<ga, 256>>>();

    dim3 gp(L_ / 64, C_ / 64, N_B);
    gemm_proj_kernel<<<gp, 256>>>(x, pw, pb, out);

    if (out_size > NCL) {
        int extra = out_size - NCL;
        int nm = in_sizes[1] < extra ? in_sizes[1] : extra;
        mask_copy_kernel<<<(nm + 255) / 256, 256>>>(mask, out, nm);
    }
}

// round 13
// speedup vs baseline: 1.0661x; 1.0661x over previous
#include <cuda_runtime.h>
#include <math.h>

#define N_B   2
#define C_    256
#define L_    4096
#define G_    8
#define CPG   32
#define HEADS 4
#define HD    64
#define EPSV  1e-5f
#define NCL   (N_B * C_ * L_)   // 2097152

// attention dynamic smem layout (float offsets)
#define QS2_OFF 0                // 64 x 128  Q duplicated along i (32 KB)
#define KPD_OFF 8192             // K: 64x64  /  P-dup: 64x128 (aliased, 32 KB)
#define VST_OFF 16384            // 64 x 68   V transposed [j][c] (17 KB)
#define ATTN_SMEM_FLOATS 20736
#define ATTN_SMEM_BYTES  (ATTN_SMEM_FLOATS * 4)   // 82944

// ---------------- f32x2 helpers ---------------------------------------------
__device__ __forceinline__ void fma2(unsigned long long& d,
                                     unsigned long long a,
                                     unsigned long long b) {
    asm("fma.rn.f32x2 %0, %1, %2, %0;" : "+l"(d) : "l"(a), "l"(b));
}
__device__ __forceinline__ void mul2(unsigned long long& d, unsigned long long a) {
    asm("mul.rn.f32x2 %0, %0, %1;" : "+l"(d) : "l"(a));
}
__device__ __forceinline__ unsigned long long pk2(float lo, float hi) {
    unsigned long long r;
    asm("mov.b64 %0, {%1, %2};" : "=l"(r) : "f"(lo), "f"(hi));
    return r;
}
__device__ __forceinline__ void upk2(unsigned long long v, float& lo, float& hi) {
    asm("mov.b64 {%0, %1}, %2;" : "=f"(lo), "=f"(hi) : "l"(v));
}

// ---------------- scratch (static device globals; no allocation) ------------
__device__ float g_xn[NCL];
__device__ float g_q [NCL];
__device__ float g_k [NCL];
__device__ float g_v [NCL];
__device__ float g_ao[NCL];
__device__ float g_stats[N_B * G_ * 2];

// ---------------- GroupNorm: stats ------------------------------------------
__global__ void gn_stats_kernel(const float* __restrict__ x) {
    int ng = blockIdx.x;
    const float4* base = (const float4*)(x + (size_t)ng * CPG * L_);
    float s1 = 0.f, s2 = 0.f;
    const int nv = CPG * L_ / 4;
    for (int i = threadIdx.x; i < nv; i += 256) {
        float4 v = base[i];
        s1 += (v.x + v.y) + (v.z + v.w);
        s2 += (v.x * v.x + v.y * v.y) + (v.z * v.z + v.w * v.w);
    }
    __shared__ float r1[256], r2[256];
    r1[threadIdx.x] = s1; r2[threadIdx.x] = s2;
    __syncthreads();
    for (int s = 128; s > 0; s >>= 1) {
        if (threadIdx.x < s) {
            r1[threadIdx.x] += r1[threadIdx.x + s];
            r2[threadIdx.x] += r2[threadIdx.x + s];
        }
        __syncthreads();
    }
    if (threadIdx.x == 0) {
        float cnt  = (float)(CPG * L_);
        float mean = r1[0] / cnt;
        float var  = r2[0] / cnt - mean * mean;
        g_stats[ng * 2 + 0] = mean;
        g_stats[ng * 2 + 1] = rsqrtf(var + EPSV);
    }
}

// ---------------- GroupNorm: apply ------------------------------------------
__global__ void gn_apply_kernel(const float* __restrict__ x,
                                const float* __restrict__ w,
                                const float* __restrict__ b) {
    int i = blockIdx.x * blockDim.x + threadIdx.x;
    if (i >= NCL / 4) return;
    int e  = i * 4;
    int c  = (e / L_) & (C_ - 1);
    int ng = e / (CPG * L_);
    float mean = g_stats[ng * 2 + 0], rstd = g_stats[ng * 2 + 1];
    float sw = w[c] * rstd;
    float sb = b[c] - mean * sw;
    float4 xv = ((const float4*)x)[i];
    float4 o;
    o.x = xv.x * sw + sb; o.y = xv.y * sw + sb;
    o.z = xv.z * sw + sb; o.w = xv.w * sw + sb;
    ((float4*)g_xn)[i] = o;
}

// ---------------- QKV conv1x1 GEMM (unchanged, known-good) ------------------
__global__ void __launch_bounds__(256) gemm_qkv_kernel(
    const float* __restrict__ qw, const float* __restrict__ qb,
    const float* __restrict__ kw, const float* __restrict__ kb,
    const float* __restrict__ vw, const float* __restrict__ vb) {

    int z = blockIdx.z;
    int batch = z / 3, which = z - batch * 3;
    const float* w; const float* bia; float* outp;
    if      (which == 0) { w = qw; bia = qb; outp = g_q; }
    else if (which == 1) { w = kw; bia = kb; outp = g_k; }
    else                 { w = vw; bia = vb; outp = g_v; }

    const float* B   = g_xn + (size_t)batch * C_ * L_;
    float*       Out = outp + (size_t)batch * C_ * L_;
    int m0 = blockIdx.y * 64, n0 = blockIdx.x * 64;

    __shared__ __align__(16) float As[16][68];
    __shared__ __align__(16) float Bs[16][64];

    int tx = threadIdx.x & 15, ty = threadIdx.x >> 4;
    float acc[4][4];
#pragma unroll
    for (int a = 0; a < 4; a++)
#pragma unroll
        for (int c = 0; c < 4; c++) acc[a][c] = 0.f;

    for (int k0 = 0; k0 < C_; k0 += 16) {
#pragma unroll
        for (int it = 0; it < 4; ++it) {
            int idx = threadIdx.x + it * 256;
            int kk = idx & 15, mm = idx >> 4;
            As[kk][mm] = w[(m0 + mm) * C_ + k0 + kk];
        }
#pragma unroll
        for (int it = 0; it < 4; ++it) {
            int idx = threadIdx.x + it * 256;
            int nn = idx & 63, kk = idx >> 6;
            Bs[kk][nn] = B[(size_t)(k0 + kk) * L_ + n0 + nn];
        }
        __syncthreads();
#pragma unroll
        for (int kk = 0; kk < 16; kk++) {
            float4 aa = *(const float4*)&As[kk][ty * 4];
            float4 bb = *(const float4*)&Bs[kk][tx * 4];
            acc[0][0] += aa.x * bb.x; acc[0][1] += aa.x * bb.y; acc[0][2] += aa.x * bb.z; acc[0][3] += aa.x * bb.w;
            acc[1][0] += aa.y * bb.x; acc[1][1] += aa.y * bb.y; acc[1][2] += aa.y * bb.z; acc[1][3] += aa.y * bb.w;
            acc[2][0] += aa.z * bb.x; acc[2][1] += aa.z * bb.y; acc[2][2] += aa.z * bb.z; acc[2][3] += aa.z * bb.w;
            acc[3][0] += aa.w * bb.x; acc[3][1] += aa.w * bb.y; acc[3][2] += aa.w * bb.z; acc[3][3] += aa.w * bb.w;
        }
        __syncthreads();
    }
#pragma unroll
    for (int im = 0; im < 4; im++) {
        int m = m0 + ty * 4 + im;
        float bv = bia[m];
        float4 o;
        o.x = acc[im][0] + bv; o.y = acc[im][1] + bv;
        o.z = acc[im][2] + bv; o.w = acc[im][3] + bv;
        *(float4*)&Out[(size_t)m * L_ + n0 + tx * 4] = o;
    }
}

// ---------------- Flash attention: Bq=64, Bk=64, packed f32x2 ---------------
__global__ void __launch_bounds__(256) attn_kernel() {
    extern __shared__ __align__(16) float sm[];
    float* Qs2 = sm + QS2_OFF;   // [c][2i] dup, row stride 128
    float* KPd = sm + KPD_OFF;   // K: [c][j] stride 64 ; later P: [j][2i] dup stride 128
    float* VsT = sm + VST_OFF;   // [j][c] stride 68

    int l0 = blockIdx.x * 64;
    int h  = blockIdx.y;
    int n  = blockIdx.z;
    int chbase = n * C_ + h * HD;
    const float* qp = g_q + (size_t)chbase * L_;
    const float* kp = g_k + (size_t)chbase * L_;
    const float* vp = g_v + (size_t)chbase * L_;

    int t  = threadIdx.x;
    int tx = t & 15, ty = t >> 4;

    // load Q tile duplicated: Qs2[c*128 + 2i] = Qs2[c*128 + 2i + 1] = q[c][l0+i]
#pragma unroll
    for (int it = 0; it < 4; ++it) {
        int fidx = t + it * 256;
        int c = fidx >> 4, i4 = fidx & 15;
        float4 q = *(const float4*)(qp + (size_t)c * L_ + l0 + 4 * i4);
        *(float4*)(Qs2 + c * 128 + 8 * i4)     = make_float4(q.x, q.x, q.y, q.y);
        *(float4*)(Qs2 + c * 128 + 8 * i4 + 4) = make_float4(q.z, q.z, q.w, q.w);
    }

    unsigned long long O2[2][4];   // [c-pair][i-row]
#pragma unroll
    for (int p = 0; p < 2; p++)
#pragma unroll
        for (int r = 0; r < 4; r++) O2[p][r] = 0ull;
    float m_run[4], l_run[4];
#pragma unroll
    for (int r = 0; r < 4; r++) { m_run[r] = -INFINITY; l_run[r] = 0.f; }
    __syncthreads();

    const float scale = 0.125f;   // hd^-0.5

    for (int kt = 0; kt < 64; ++kt) {
        int k0 = kt * 64;

        // K tile [c][j] stride 64
#pragma unroll
        for (int it = 0; it < 4; ++it) {
            int fidx = t + it * 256;
            int c = fidx >> 4, j4 = fidx & 15;
            *(float4*)(KPd + c * 64 + 4 * j4) =
                *(const float4*)(kp + (size_t)c * L_ + k0 + 4 * j4);
        }
        // V transposed [j][c] stride 68 (coalesced LDG, conflict-free STS.128)
        {
            int j = t & 63;
#pragma unroll
            for (int it = 0; it < 4; ++it) {
                int c0 = 4 * ((t >> 6) + it * 4);
                float4 v;
                v.x = vp[(size_t)(c0 + 0) * L_ + k0 + j];
                v.y = vp[(size_t)(c0 + 1) * L_ + k0 + j];
                v.z = vp[(size_t)(c0 + 2) * L_ + k0 + j];
                v.w = vp[(size_t)(c0 + 3) * L_ + k0 + j];
                *(float4*)(VsT + j * 68 + c0) = v;
            }
        }
        __syncthreads();

        // ---- QK: S[i][j] = sum_c Q[c][i] K[c][j], packed along j ----
        unsigned long long s2[4][2];
#pragma unroll
        for (int r = 0; r < 4; r++) { s2[r][0] = 0ull; s2[r][1] = 0ull; }
        {
            const float* qbase = Qs2 + 8 * ty;
            const float* kbase = KPd + 4 * tx;
#pragma unroll 8
            for (int c = 0; c < 64; c++) {
                ulonglong2 q01 = *(const ulonglong2*)(qbase + c * 128);
                ulonglong2 q23 = *(const ulonglong2*)(qbase + c * 128 + 4);
                ulonglong2 kk  = *(const ulonglong2*)(kbase + c * 64);
                fma2(s2[0][0], q01.x, kk.x); fma2(s2[0][1], q01.x, kk.y);
                fma2(s2[1][0], q01.y, kk.x); fma2(s2[1][1], q01.y, kk.y);
                fma2(s2[2][0], q23.x, kk.x); fma2(s2[2][1], q23.x, kk.y);
                fma2(s2[3][0], q23.y, kk.x); fma2(s2[3][1], q23.y, kk.y);
            }
        }
        __syncthreads();   // all QK reads of K done before P overwrites it

        // ---- online softmax (row i; 16 tx-lanes per row) ----
        float pbuf[4][4];
#pragma unroll
        for (int r = 0; r < 4; r++) {
            float v0, v1, v2, v3;
            upk2(s2[r][0], v0, v1);
            upk2(s2[r][1], v2, v3);
            v0 *= scale; v1 *= scale; v2 *= scale; v3 *= scale;
            float mloc = fmaxf(fmaxf(v0, v1), fmaxf(v2, v3));
#pragma unroll
            for (int off = 8; off > 0; off >>= 1)
                mloc = fmaxf(mloc, __shfl_xor_sync(0xffffffffu, mloc, off));
            float mnew  = fmaxf(m_run[r], mloc);
            float alpha = __expf(m_run[r] - mnew);
            float p0 = __expf(v0 - mnew);
            float p1 = __expf(v1 - mnew);
            float p2 = __expf(v2 - mnew);
            float p3 = __expf(v3 - mnew);
            float sl = (p0 + p1) + (p2 + p3);
#pragma unroll
            for (int off = 8; off > 0; off >>= 1)
                sl += __shfl_xor_sync(0xffffffffu, sl, off);
            l_run[r] = l_run[r] * alpha + sl;
            m_run[r] = mnew;
            unsigned long long a2 = pk2(alpha, alpha);
            mul2(O2[0][r], a2);
            mul2(O2[1][r], a2);
            pbuf[r][0] = p0; pbuf[r][1] = p1; pbuf[r][2] = p2; pbuf[r][3] = p3;
        }
        // store P duplicated along i into KPd (aliases K), XOR-swizzled, stride 128
        {
            int sbase = 8 * (ty ^ (tx & 7));
#pragma unroll
            for (int cc = 0; cc < 4; cc++) {
                float* dst = KPd + (4 * tx + cc) * 128 + sbase;
                *(float4*)dst       = make_float4(pbuf[0][cc], pbuf[0][cc],
                                                  pbuf[1][cc], pbuf[1][cc]);
                *(float4*)(dst + 4) = make_float4(pbuf[2][cc], pbuf[2][cc],
                                                  pbuf[3][cc], pbuf[3][cc]);
            }
        }
        __syncthreads();

        // ---- PV: O[c][i] += V[c][j] * P[i][j], packed along c ----
#pragma unroll 4
        for (int j = 0; j < 64; j++) {
            ulonglong2 va = *(const ulonglong2*)(VsT + j * 68 + 4 * tx);
            const float* pb = KPd + j * 128 + 8 * (ty ^ ((j >> 2) & 7));
            ulonglong2 p01 = *(const ulonglong2*)(pb);
            ulonglong2 p23 = *(const ulonglong2*)(pb + 4);
            fma2(O2[0][0], va.x, p01.x); fma2(O2[1][0], va.y, p01.x);
            fma2(O2[0][1], va.x, p01.y); fma2(O2[1][1], va.y, p01.y);
            fma2(O2[0][2], va.x, p23.x); fma2(O2[1][2], va.y, p23.x);
            fma2(O2[0][3], va.x, p23.y); fma2(O2[1][3], va.y, p23.y);
        }
        __syncthreads();   // PV done before next iteration's K/V overwrite
    }

    // normalize and store
    float* ao = g_ao + (size_t)chbase * L_;
#pragma unroll
    for (int r = 0; r < 4; r++) {
        float inv = 1.f / l_run[r];
        int li = l0 + 4 * ty + r;
#pragma unroll
        for (int p = 0; p < 2; p++) {
            float lo, hi;
            upk2(O2[p][r], lo, hi);
            int c = 4 * tx + 2 * p;
            ao[(size_t)(c + 0) * L_ + li] = lo * inv;
            ao[(size_t)(c + 1) * L_ + li] = hi * inv;
        }
    }
}

// ---------------- projection + bias + residual (unchanged) ------------------
__global__ void __launch_bounds__(256) gemm_proj_kernel(
    const float* __restrict__ x,
    const float* __restrict__ pw, const float* __restrict__ pb,
    float* __restrict__ out) {

    int batch = blockIdx.z;
    const float* B  = g_ao + (size_t)batch * C_ * L_;
    const float* xb = x    + (size_t)batch * C_ * L_;
    float*       Ob = out  + (size_t)batch * C_ * L_;
    int m0 = blockIdx.y * 64, n0 = blockIdx.x * 64;

    __shared__ __align__(16) float As[16][68];
    __shared__ __align__(16) float Bs[16][64];

    int tx = threadIdx.x & 15, ty = threadIdx.x >> 4;
    float acc[4][4];
#pragma unroll
    for (int a = 0; a < 4; a++)
#pragma unroll
        for (int c = 0; c < 4; c++) acc[a][c] = 0.f;

    for (int k0 = 0; k0 < C_; k0 += 16) {
#pragma unroll
        for (int it = 0; it < 4; ++it) {
            int idx = threadIdx.x + it * 256;
            int kk = idx & 15, mm = idx >> 4;
            As[kk][mm] = pw[(m0 + mm) * C_ + k0 + kk];
        }
#pragma unroll
        for (int it = 0; it < 4; ++it) {
            int idx = threadIdx.x + it * 256;
            int nn = idx & 63, kk = idx >> 6;
            Bs[kk][nn] = B[(size_t)(k0 + kk) * L_ + n0 + nn];
        }
        __syncthreads();
#pragma unroll
        for (int kk = 0; kk < 16; kk++) {
            float4 aa = *(const float4*)&As[kk][ty * 4];
            float4 bb = *(const float4*)&Bs[kk][tx * 4];
            acc[0][0] += aa.x * bb.x; acc[0][1] += aa.x * bb.y; acc[0][2] += aa.x * bb.z; acc[0][3] += aa.x * bb.w;
            acc[1][0] += aa.y * bb.x; acc[1][1] += aa.y * bb.y; acc[1][2] += aa.y * bb.z; acc[1][3] += aa.y * bb.w;
            acc[2][0] += aa.z * bb.x; acc[2][1] += aa.z * bb.y; acc[2][2] += aa.z * bb.z; acc[2][3] += aa.z * bb.w;
            acc[3][0] += aa.w * bb.x; acc[3][1] += aa.w * bb.y; acc[3][2] += aa.w * bb.z; acc[3][3] += aa.w * bb.w;
        }
        __syncthreads();
    }
#pragma unroll
    for (int im = 0; im < 4; im++) {
        int m = m0 + ty * 4 + im;
        float bv = pb[m];
        size_t off = (size_t)m * L_ + n0 + tx * 4;
        float4 xv = *(const float4*)&xb[off];
        float4 o;
        o.x = acc[im][0] + bv + xv.x; o.y = acc[im][1] + bv + xv.y;
        o.z = acc[im][2] + bv + xv.z; o.w = acc[im][3] + bv + xv.w;
        *(float4*)&Ob[off] = o;
    }
}

// ---------------- mask pass-through (int32 -> float) ------------------------
__global__ void mask_copy_kernel(const int* __restrict__ mask,
                                 float* __restrict__ out, int nmask) {
    int i = blockIdx.x * blockDim.x + threadIdx.x;
    if (i < nmask) out[NCL + i] = (float)mask[i];
}

// ---------------- launch -----------------------------------------------------
extern "C" void kernel_launch(void* const* d_in, const int* in_sizes, int n_in,
                              void* d_out, int out_size) {
    const float* x    = (const float*)d_in[0];
    const int*   mask = (const int*)  d_in[1];
    const float* nw   = (const float*)d_in[2];
    const float* nb   = (const float*)d_in[3];
    const float* qw   = (const float*)d_in[4];
    const float* qb   = (const float*)d_in[5];
    const float* kw   = (const float*)d_in[6];
    const float* kb   = (const float*)d_in[7];
    const float* vw   = (const float*)d_in[8];
    const float* vb   = (const float*)d_in[9];
    const float* pw   = (const float*)d_in[10];
    const float* pb   = (const float*)d_in[11];
    float* out = (float*)d_out;

    cudaFuncSetAttribute(attn_kernel,
                         cudaFuncAttributeMaxDynamicSharedMemorySize,
                         ATTN_SMEM_BYTES);

    gn_stats_kernel<<<N_B * G_, 256>>>(x);
    gn_apply_kernel<<<(NCL / 4 + 255) / 256, 256>>>(x, nw, nb);

    dim3 gq(L_ / 64, C_ / 64, N_B * 3);
    gemm_qkv_kernel<<<gq, 256>>>(qw, qb, kw, kb, vw, vb);

    dim3 ga(L_ / 64, HEADS, N_B);
    attn_kernel<<<ga, 256, ATTN_SMEM_BYTES>>>();

    dim3 gp(L_ / 64, C_ / 64, N_B);
    gemm_proj_kernel<<<gp, 256>>>(x, pw, pb, out);

    if (out_size > NCL) {
        int extra = out_size - NCL;
        int nm = in_sizes[1] < extra ? in_sizes[1] : extra;
        mask_copy_kernel<<<(nm + 255) / 256, 256>>>(mask, out, nm);
    }
}

// round 15
// speedup vs baseline: 1.4509x; 1.3610x over previous
#include <cuda_runtime.h>
#include <math.h>

#define N_B   2
#define C_    256
#define L_    4096
#define G_    8
#define CPG   32
#define HEADS 4
#define HD    64
#define EPSV  1e-5f
#define NCL   (N_B * C_ * L_)   // 2097152

// attention dynamic smem layout (float offsets)
// Qs: [c][i]  64 x 128, stride 132  ->  8448 floats
// KP: K [c][j] 64 x 64 stride 68  /  P [j][i] 64 x 128 stride 132 (aliased) -> 8448
// Vs: [j][c]  64 x 64, stride 68  ->  4352
#define QS_OFF 0
#define KP_OFF 8448
#define VS_OFF 16896
#define ATTN_SMEM_FLOATS 21248
#define ATTN_SMEM_BYTES  (ATTN_SMEM_FLOATS * 4)   // 84992

// ---------------- f32x2 helpers ---------------------------------------------
__device__ __forceinline__ void fma2(unsigned long long& d,
                                     unsigned long long a,
                                     unsigned long long b) {
    asm("fma.rn.f32x2 %0, %1, %2, %0;" : "+l"(d) : "l"(a), "l"(b));
}
__device__ __forceinline__ void mul2(unsigned long long& d, unsigned long long a) {
    asm("mul.rn.f32x2 %0, %0, %1;" : "+l"(d) : "l"(a));
}
__device__ __forceinline__ unsigned long long pk2(float lo, float hi) {
    unsigned long long r;
    asm("mov.b64 %0, {%1, %2};" : "=l"(r) : "f"(lo), "f"(hi));
    return r;
}
__device__ __forceinline__ void upk2(unsigned long long v, float& lo, float& hi) {
    asm("mov.b64 {%0, %1}, %2;" : "=f"(lo), "=f"(hi) : "l"(v));
}

// ---------------- scratch (static device globals; no allocation) ------------
__device__ float g_xn[NCL];
__device__ float g_q [NCL];
__device__ float g_k [NCL];
__device__ float g_v [NCL];
__device__ float g_ao[NCL];
__device__ float g_stats[N_B * G_ * 2];

// ---------------- GroupNorm: stats ------------------------------------------
__global__ void gn_stats_kernel(const float* __restrict__ x) {
    int ng = blockIdx.x;
    const float4* base = (const float4*)(x + (size_t)ng * CPG * L_);
    float s1 = 0.f, s2 = 0.f;
    const int nv = CPG * L_ / 4;
    for (int i = threadIdx.x; i < nv; i += 256) {
        float4 v = base[i];
        s1 += (v.x + v.y) + (v.z + v.w);
        s2 += (v.x * v.x + v.y * v.y) + (v.z * v.z + v.w * v.w);
    }
    __shared__ float r1[256], r2[256];
    r1[threadIdx.x] = s1; r2[threadIdx.x] = s2;
    __syncthreads();
    for (int s = 128; s > 0; s >>= 1) {
        if (threadIdx.x < s) {
            r1[threadIdx.x] += r1[threadIdx.x + s];
            r2[threadIdx.x] += r2[threadIdx.x + s];
        }
        __syncthreads();
    }
    if (threadIdx.x == 0) {
        float cnt  = (float)(CPG * L_);
        float mean = r1[0] / cnt;
        float var  = r2[0] / cnt - mean * mean;
        g_stats[ng * 2 + 0] = mean;
        g_stats[ng * 2 + 1] = rsqrtf(var + EPSV);
    }
}

// ---------------- GroupNorm: apply ------------------------------------------
__global__ void gn_apply_kernel(const float* __restrict__ x,
                                const float* __restrict__ w,
                                const float* __restrict__ b) {
    int i = blockIdx.x * blockDim.x + threadIdx.x;
    if (i >= NCL / 4) return;
    int e  = i * 4;
    int c  = (e / L_) & (C_ - 1);
    int ng = e / (CPG * L_);
    float mean = g_stats[ng * 2 + 0], rstd = g_stats[ng * 2 + 1];
    float sw = w[c] * rstd;
    float sb = b[c] - mean * sw;
    float4 xv = ((const float4*)x)[i];
    float4 o;
    o.x = xv.x * sw + sb; o.y = xv.y * sw + sb;
    o.z = xv.z * sw + sb; o.w = xv.w * sw + sb;
    ((float4*)g_xn)[i] = o;
}

// ---------------- QKV conv1x1 GEMM (unchanged, known-good) ------------------
__global__ void __launch_bounds__(256) gemm_qkv_kernel(
    const float* __restrict__ qw, const float* __restrict__ qb,
    const float* __restrict__ kw, const float* __restrict__ kb,
    const float* __restrict__ vw, const float* __restrict__ vb) {

    int z = blockIdx.z;
    int batch = z / 3, which = z - batch * 3;
    const float* w; const float* bia; float* outp;
    if      (which == 0) { w = qw; bia = qb; outp = g_q; }
    else if (which == 1) { w = kw; bia = kb; outp = g_k; }
    else                 { w = vw; bia = vb; outp = g_v; }

    const float* B   = g_xn + (size_t)batch * C_ * L_;
    float*       Out = outp + (size_t)batch * C_ * L_;
    int m0 = blockIdx.y * 64, n0 = blockIdx.x * 64;

    __shared__ __align__(16) float As[16][68];
    __shared__ __align__(16) float Bs[16][64];

    int tx = threadIdx.x & 15, ty = threadIdx.x >> 4;
    float acc[4][4];
#pragma unroll
    for (int a = 0; a < 4; a++)
#pragma unroll
        for (int c = 0; c < 4; c++) acc[a][c] = 0.f;

    for (int k0 = 0; k0 < C_; k0 += 16) {
#pragma unroll
        for (int it = 0; it < 4; ++it) {
            int idx = threadIdx.x + it * 256;
            int kk = idx & 15, mm = idx >> 4;
            As[kk][mm] = w[(m0 + mm) * C_ + k0 + kk];
        }
#pragma unroll
        for (int it = 0; it < 4; ++it) {
            int idx = threadIdx.x + it * 256;
            int nn = idx & 63, kk = idx >> 6;
            Bs[kk][nn] = B[(size_t)(k0 + kk) * L_ + n0 + nn];
        }
        __syncthreads();
#pragma unroll
        for (int kk = 0; kk < 16; kk++) {
            float4 aa = *(const float4*)&As[kk][ty * 4];
            float4 bb = *(const float4*)&Bs[kk][tx * 4];
            acc[0][0] += aa.x * bb.x; acc[0][1] += aa.x * bb.y; acc[0][2] += aa.x * bb.z; acc[0][3] += aa.x * bb.w;
            acc[1][0] += aa.y * bb.x; acc[1][1] += aa.y * bb.y; acc[1][2] += aa.y * bb.z; acc[1][3] += aa.y * bb.w;
            acc[2][0] += aa.z * bb.x; acc[2][1] += aa.z * bb.y; acc[2][2] += aa.z * bb.z; acc[2][3] += aa.z * bb.w;
            acc[3][0] += aa.w * bb.x; acc[3][1] += aa.w * bb.y; acc[3][2] += aa.w * bb.z; acc[3][3] += aa.w * bb.w;
        }
        __syncthreads();
    }
#pragma unroll
    for (int im = 0; im < 4; im++) {
        int m = m0 + ty * 4 + im;
        float bv = bia[m];
        float4 o;
        o.x = acc[im][0] + bv; o.y = acc[im][1] + bv;
        o.z = acc[im][2] + bv; o.w = acc[im][3] + bv;
        *(float4*)&Out[(size_t)m * L_ + n0 + tx * 4] = o;
    }
}

// ---------------- Flash attention: Bq=128, Bk=64, 8i x 4j per thread --------
// S/O packed along i (natural Q/P pairs); K/V dup built in registers.
__global__ void __launch_bounds__(256, 2) attn_kernel() {
    extern __shared__ __align__(16) float sm[];
    float* Qs = sm + QS_OFF;   // [c][i] stride 132
    float* KP = sm + KP_OFF;   // K: [c][j] stride 68 ; P: [j][i] stride 132
    float* Vs = sm + VS_OFF;   // [j][c] stride 68

    int l0 = blockIdx.x * 128;
    int h  = blockIdx.y;
    int n  = blockIdx.z;
    int chbase = n * C_ + h * HD;
    const float* qp = g_q + (size_t)chbase * L_;
    const float* kp = g_k + (size_t)chbase * L_;
    const float* vp = g_v + (size_t)chbase * L_;

    int t  = threadIdx.x;
    int tx = t & 15, ty = t >> 4;

    // Q fill: [c][i], straight copy, coalesced
#pragma unroll
    for (int it = 0; it < 8; ++it) {
        int fidx = t + it * 256;
        int c = fidx >> 5, i4 = fidx & 31;
        *(float4*)(Qs + c * 132 + 4 * i4) =
            *(const float4*)(qp + (size_t)c * L_ + l0 + 4 * i4);
    }

    unsigned long long O2[4][4];   // [i-pair][cc] : i = 8ty+2ip(+1), c = 4tx+cc
#pragma unroll
    for (int ip = 0; ip < 4; ip++)
#pragma unroll
        for (int cc = 0; cc < 4; cc++) O2[ip][cc] = 0ull;
    float m_run[8], l_run[8];
#pragma unroll
    for (int r = 0; r < 8; r++) { m_run[r] = -INFINITY; l_run[r] = 0.f; }
    __syncthreads();

    const float scale = 0.125f;   // hd^-0.5

    for (int kt = 0; kt < 64; ++kt) {
        int k0 = kt * 64;

        // K fill [c][j] stride 68
#pragma unroll
        for (int it = 0; it < 4; ++it) {
            int fidx = t + it * 256;
            int c = fidx >> 4, j4 = fidx & 15;
            *(float4*)(KP + c * 68 + 4 * j4) =
                *(const float4*)(kp + (size_t)c * L_ + k0 + 4 * j4);
        }
        // V fill transposed [j][c] stride 68
        {
            int j = t & 63;
#pragma unroll
            for (int it = 0; it < 4; ++it) {
                int c0 = 4 * ((t >> 6) + it * 4);
                float4 v;
                v.x = vp[(size_t)(c0 + 0) * L_ + k0 + j];
                v.y = vp[(size_t)(c0 + 1) * L_ + k0 + j];
                v.z = vp[(size_t)(c0 + 2) * L_ + k0 + j];
                v.w = vp[(size_t)(c0 + 3) * L_ + k0 + j];
                *(float4*)(Vs + j * 68 + c0) = v;
            }
        }
        __syncthreads();

        // ---- QK: S[i][j] = sum_c Q[c][i] K[c][j], packed along i ----
        unsigned long long s2[4][4];   // [i-pair][jj]
#pragma unroll
        for (int ip = 0; ip < 4; ip++)
#pragma unroll
            for (int jj = 0; jj < 4; jj++) s2[ip][jj] = 0ull;
        {
            const float* qb = Qs + 8 * ty;
            const float* kb = KP + 4 * tx;
#pragma unroll 8
            for (int c = 0; c < 64; c++) {
                ulonglong2 qA = *(const ulonglong2*)(qb + c * 132);      // pairs (i0,i1),(i2,i3)
                ulonglong2 qB = *(const ulonglong2*)(qb + c * 132 + 4);  // pairs (i4,i5),(i6,i7)
                float4 kf = *(const float4*)(kb + c * 68);
                unsigned long long kd0 = pk2(kf.x, kf.x);
                unsigned long long kd1 = pk2(kf.y, kf.y);
                unsigned long long kd2 = pk2(kf.z, kf.z);
                unsigned long long kd3 = pk2(kf.w, kf.w);
                fma2(s2[0][0], qA.x, kd0); fma2(s2[0][1], qA.x, kd1);
                fma2(s2[0][2], qA.x, kd2); fma2(s2[0][3], qA.x, kd3);
                fma2(s2[1][0], qA.y, kd0); fma2(s2[1][1], qA.y, kd1);
                fma2(s2[1][2], qA.y, kd2); fma2(s2[1][3], qA.y, kd3);
                fma2(s2[2][0], qB.x, kd0); fma2(s2[2][1], qB.x, kd1);
                fma2(s2[2][2], qB.x, kd2); fma2(s2[2][3], qB.x, kd3);
                fma2(s2[3][0], qB.y, kd0); fma2(s2[3][1], qB.y, kd1);
                fma2(s2[3][2], qB.y, kd2); fma2(s2[3][3], qB.y, kd3);
            }
        }
        __syncthreads();   // K reads done before P overwrites the buffer

        // ---- online softmax: 8 rows (2 per i-pair) ----
#pragma unroll
        for (int ip = 0; ip < 4; ip++) {
            float a0, b0, a1, b1, a2, b2, a3, b3;
            upk2(s2[ip][0], a0, b0); upk2(s2[ip][1], a1, b1);
            upk2(s2[ip][2], a2, b2); upk2(s2[ip][3], a3, b3);
            a0 *= scale; a1 *= scale; a2 *= scale; a3 *= scale;
            b0 *= scale; b1 *= scale; b2 *= scale; b3 *= scale;
            int rA = 2 * ip, rB = 2 * ip + 1;

            float mA = fmaxf(fmaxf(a0, a1), fmaxf(a2, a3));
            float mB = fmaxf(fmaxf(b0, b1), fmaxf(b2, b3));
#pragma unroll
            for (int off = 8; off > 0; off >>= 1) {
                mA = fmaxf(mA, __shfl_xor_sync(0xffffffffu, mA, off));
                mB = fmaxf(mB, __shfl_xor_sync(0xffffffffu, mB, off));
            }
            float mnA = fmaxf(m_run[rA], mA);
            float mnB = fmaxf(m_run[rB], mB);
            float alA = __expf(m_run[rA] - mnA);
            float alB = __expf(m_run[rB] - mnB);
            m_run[rA] = mnA; m_run[rB] = mnB;
            float pA0 = __expf(a0 - mnA), pA1 = __expf(a1 - mnA);
            float pA2 = __expf(a2 - mnA), pA3 = __expf(a3 - mnA);
            float pB0 = __expf(b0 - mnB), pB1 = __expf(b1 - mnB);
            float pB2 = __expf(b2 - mnB), pB3 = __expf(b3 - mnB);
            float sA = (pA0 + pA1) + (pA2 + pA3);
            float sB = (pB0 + pB1) + (pB2 + pB3);
#pragma unroll
            for (int off = 8; off > 0; off >>= 1) {
                sA += __shfl_xor_sync(0xffffffffu, sA, off);
                sB += __shfl_xor_sync(0xffffffffu, sB, off);
            }
            l_run[rA] = l_run[rA] * alA + sA;
            l_run[rB] = l_run[rB] * alB + sB;

            unsigned long long al2 = pk2(alA, alB);
            mul2(O2[ip][0], al2); mul2(O2[ip][1], al2);
            mul2(O2[ip][2], al2); mul2(O2[ip][3], al2);

            // store P pairs (rowA,rowB) to P[j][i], j = 4tx+jj
            float* pst = KP + (4 * tx) * 132 + 8 * ty + 2 * ip;
            *(float2*)(pst)           = make_float2(pA0, pB0);
            *(float2*)(pst + 132)     = make_float2(pA1, pB1);
            *(float2*)(pst + 2 * 132) = make_float2(pA2, pB2);
            *(float2*)(pst + 3 * 132) = make_float2(pA3, pB3);
        }
        __syncthreads();

        // ---- PV: O[i][c] += P[i][j] V[c][j], packed along i ----
        {
            const float* pbase = KP + 8 * ty;
            const float* vbase = Vs + 4 * tx;
#pragma unroll 4
            for (int j = 0; j < 64; j++) {
                float4 vf = *(const float4*)(vbase + j * 68);
                ulonglong2 pA = *(const ulonglong2*)(pbase + j * 132);
                ulonglong2 pB = *(const ulonglong2*)(pbase + j * 132 + 4);
                unsigned long long vd0 = pk2(vf.x, vf.x);
                unsigned long long vd1 = pk2(vf.y, vf.y);
                unsigned long long vd2 = pk2(vf.z, vf.z);
                unsigned long long vd3 = pk2(vf.w, vf.w);
                fma2(O2[0][0], vd0, pA.x); fma2(O2[0][1], vd1, pA.x);
                fma2(O2[0][2], vd2, pA.x); fma2(O2[0][3], vd3, pA.x);
                fma2(O2[1][0], vd0, pA.y); fma2(O2[1][1], vd1, pA.y);
                fma2(O2[1][2], vd2, pA.y); fma2(O2[1][3], vd3, pA.y);
                fma2(O2[2][0], vd0, pB.x); fma2(O2[2][1], vd1, pB.x);
                fma2(O2[2][2], vd2, pB.x); fma2(O2[2][3], vd3, pB.x);
                fma2(O2[3][0], vd0, pB.y); fma2(O2[3][1], vd1, pB.y);
                fma2(O2[3][2], vd2, pB.y); fma2(O2[3][3], vd3, pB.y);
            }
        }
        __syncthreads();   // PV reads done before next kt overwrites K/V
    }

    // normalize and store: O[i][c] -> g_ao[c][l0+i]
    float* ao = g_ao + (size_t)chbase * L_;
#pragma unroll
    for (int ip = 0; ip < 4; ip++) {
        float inv0 = 1.f / l_run[2 * ip];
        float inv1 = 1.f / l_run[2 * ip + 1];
        int li = l0 + 8 * ty + 2 * ip;
#pragma unroll
        for (int cc = 0; cc < 4; cc++) {
            float lo, hi;
            upk2(O2[ip][cc], lo, hi);
            int c = 4 * tx + cc;
            *(float2*)(ao + (size_t)c * L_ + li) = make_float2(lo * inv0, hi * inv1);
        }
    }
}

// ---------------- projection + bias + residual (unchanged) ------------------
__global__ void __launch_bounds__(256) gemm_proj_kernel(
    const float* __restrict__ x,
    const float* __restrict__ pw, const float* __restrict__ pb,
    float* __restrict__ out) {

    int batch = blockIdx.z;
    const float* B  = g_ao + (size_t)batch * C_ * L_;
    const float* xb = x    + (size_t)batch * C_ * L_;
    float*       Ob = out  + (size_t)batch * C_ * L_;
    int m0 = blockIdx.y * 64, n0 = blockIdx.x * 64;

    __shared__ __align__(16) float As[16][68];
    __shared__ __align__(16) float Bs[16][64];

    int tx = threadIdx.x & 15, ty = threadIdx.x >> 4;
    float acc[4][4];
#pragma unroll
    for (int a = 0; a < 4; a++)
#pragma unroll
        for (int c = 0; c < 4; c++) acc[a][c] = 0.f;

    for (int k0 = 0; k0 < C_; k0 += 16) {
#pragma unroll
        for (int it = 0; it < 4; ++it) {
            int idx = threadIdx.x + it * 256;
            int kk = idx & 15, mm = idx >> 4;
            As[kk][mm] = pw[(m0 + mm) * C_ + k0 + kk];
        }
#pragma unroll
        for (int it = 0; it < 4; ++it) {
            int idx = threadIdx.x + it * 256;
            int nn = idx & 63, kk = idx >> 6;
            Bs[kk][nn] = B[(size_t)(k0 + kk) * L_ + n0 + nn];
        }
        __syncthreads();
#pragma unroll
        for (int kk = 0; kk < 16; kk++) {
            float4 aa = *(const float4*)&As[kk][ty * 4];
            float4 bb = *(const float4*)&Bs[kk][tx * 4];
            acc[0][0] += aa.x * bb.x; acc[0][1] += aa.x * bb.y; acc[0][2] += aa.x * bb.z; acc[0][3] += aa.x * bb.w;
            acc[1][0] += aa.y * bb.x; acc[1][1] += aa.y * bb.y; acc[1][2] += aa.y * bb.z; acc[1][3] += aa.y * bb.w;
            acc[2][0] += aa.z * bb.x; acc[2][1] += aa.z * bb.y; acc[2][2] += aa.z * bb.z; acc[2][3] += aa.z * bb.w;
            acc[3][0] += aa.w * bb.x; acc[3][1] += aa.w * bb.y; acc[3][2] += aa.w * bb.z; acc[3][3] += aa.w * bb.w;
        }
        __syncthreads();
    }
#pragma unroll
    for (int im = 0; im < 4; im++) {
        int m = m0 + ty * 4 + im;
        float bv = pb[m];
        size_t off = (size_t)m * L_ + n0 + tx * 4;
        float4 xv = *(const float4*)&xb[off];
        float4 o;
        o.x = acc[im][0] + bv + xv.x; o.y = acc[im][1] + bv + xv.y;
        o.z = acc[im][2] + bv + xv.z; o.w = acc[im][3] + bv + xv.w;
        *(float4*)&Ob[off] = o;
    }
}

// ---------------- mask pass-through (int32 -> float) ------------------------
__global__ void mask_copy_kernel(const int* __restrict__ mask,
                                 float* __restrict__ out, int nmask) {
    int i = blockIdx.x * blockDim.x + threadIdx.x;
    if (i < nmask) out[NCL + i] = (float)mask[i];
}

// ---------------- launch -----------------------------------------------------
extern "C" void kernel_launch(void* const* d_in, const int* in_sizes, int n_in,
                              void* d_out, int out_size) {
    const float* x    = (const float*)d_in[0];
    const int*   mask = (const int*)  d_in[1];
    const float* nw   = (const float*)d_in[2];
    const float* nb   = (const float*)d_in[3];
    const float* qw   = (const float*)d_in[4];
    const float* qb   = (const float*)d_in[5];
    const float* kw   = (const float*)d_in[6];
    const float* kb   = (const float*)d_in[7];
    const float* vw   = (const float*)d_in[8];
    const float* vb   = (const float*)d_in[9];
    const float* pw   = (const float*)d_in[10];
    const float* pb   = (const float*)d_in[11];
    float* out = (float*)d_out;

    cudaFuncSetAttribute(attn_kernel,
                         cudaFuncAttributeMaxDynamicSharedMemorySize,
                         ATTN_SMEM_BYTES);

    gn_stats_kernel<<<N_B * G_, 256>>>(x);
    gn_apply_kernel<<<(NCL / 4 + 255) / 256, 256>>>(x, nw, nb);

    dim3 gq(L_ / 64, C_ / 64, N_B * 3);
    gemm_qkv_kernel<<<gq, 256>>>(qw, qb, kw, kb, vw, vb);

    dim3 ga(L_ / 128, HEADS, N_B);
    attn_kernel<<<ga, 256, ATTN_SMEM_BYTES>>>();

    dim3 gp(L_ / 64, C_ / 64, N_B);
    gemm_proj_kernel<<<gp, 256>>>(x, pw, pb, out);

    if (out_size > NCL) {
        int extra = out_size - NCL;
        int nm = in_sizes[1] < extra ? in_sizes[1] : extra;
        mask_copy_kernel<<<(nm + 255) / 256, 256>>>(mask, out, nm);
    }
}